// round 5
// baseline (speedup 1.0000x reference)
#include <cuda_runtime.h>
#include <cstdint>

// ---------------------------------------------------------------------------
// Gcs_loss, expanded form:
//   v = pred - truth, halves X = v[:,:P], Y = v[:,P:]
//   s_i = S2 - 2 * sum_b v[b,i]*rowsum[b] + P * sum_b v[b,i]^2
//   out = ( sum_i sqrt(s_i^X) + sum_i sqrt(s_i^Y) ) / (2B)
// B=32, P=1024.
//
// ONE cluster of 8 CTAs. CTA r owns column slice r (128 cols) of BOTH halves.
// Single cluster.sync (overlapped with the global loads); partials exchange
// and final combine are push-style st.async + mbarrier. No device globals,
// no global atomics, no per-replay resets.
// ---------------------------------------------------------------------------

#define GB      32
#define GP      1024
#define SCOLS   128            // columns per slice (8 slices per half)

// ---------------- tiny PTX helpers ----------------
__device__ __forceinline__ uint32_t smem_u32(const void* p) {
    uint32_t a;
    asm("{ .reg .u64 t; cvta.to.shared.u64 t, %1; cvt.u32.u64 %0, t; }"
        : "=r"(a) : "l"(p));
    return a;
}
__device__ __forceinline__ uint32_t mapa_rank(uint32_t smem_addr, uint32_t rank) {
    uint32_t r;
    asm("mapa.shared::cluster.u32 %0, %1, %2;" : "=r"(r) : "r"(smem_addr), "r"(rank));
    return r;
}
__device__ __forceinline__ void mbar_init(uint32_t mbar, uint32_t count) {
    asm volatile("mbarrier.init.shared.b64 [%0], %1;" :: "r"(mbar), "r"(count) : "memory");
}
__device__ __forceinline__ void mbar_expect_tx(uint32_t mbar, uint32_t bytes) {
    asm volatile("mbarrier.arrive.expect_tx.shared.b64 _, [%0], %1;"
                 :: "r"(mbar), "r"(bytes) : "memory");
}
__device__ __forceinline__ void mbar_wait(uint32_t mbar, uint32_t parity) {
    uint32_t done;
    asm volatile(
        "{\n\t.reg .pred p;\n\t"
        "mbarrier.try_wait.parity.acquire.cta.shared::cta.b64 p, [%1], %2;\n\t"
        "selp.b32 %0, 1, 0, p;\n\t}"
        : "=r"(done) : "r"(mbar), "r"(parity) : "memory");
    if (!done) {
        asm volatile(
            "{\n\t.reg .pred P1;\n\t"
            "WL_%=:\n\t"
            "mbarrier.try_wait.parity.acquire.cta.shared::cta.b64 P1, [%0], %1, 0x989680;\n\t"
            "@P1 bra.uni WD_%=;\n\t"
            "bra.uni WL_%=;\n\t"
            "WD_%=:\n\t}"
            :: "r"(mbar), "r"(parity) : "memory");
    }
}
__device__ __forceinline__ void st_async_b64(uint32_t dst, float a, float b, uint32_t mbar) {
    float2 v = make_float2(a, b);
    unsigned long long bits = *reinterpret_cast<unsigned long long*>(&v);
    asm volatile("st.async.shared::cluster.mbarrier::complete_tx::bytes.b64 [%0], %1, [%2];"
                 :: "r"(dst), "l"(bits), "r"(mbar) : "memory");
}
__device__ __forceinline__ void st_async_b32(uint32_t dst, float a, uint32_t mbar) {
    asm volatile("st.async.shared::cluster.mbarrier::complete_tx::bytes.b32 [%0], %1, [%2];"
                 :: "r"(dst), "r"(__float_as_uint(a)), "r"(mbar) : "memory");
}

// ---------------------------------------------------------------------------

__global__ void __launch_bounds__(1024, 1) __cluster_dims__(8, 1, 1)
gcs_loss_kernel(const float* __restrict__ pred,
                const float* __restrict__ truth,
                float* __restrict__ out)
{
    __shared__ float  sv[2 * GB * SCOLS];      // 32 KB: [half][row][col]
    __shared__ float2 s_pX[8][GB];             // pushed (rowsumX, sqX) per src rank/row
    __shared__ float2 s_pY[8][GB];             // pushed (rowsumY, sqY)
    __shared__ float  s_bsums[8];              // rank0: per-rank block sums
    __shared__ float  s_rowsum[2][GB];
    __shared__ float  s_S2[2];
    __shared__ float  s_red[8];
    __shared__ __align__(8) unsigned long long mbar1;   // partials exchange
    __shared__ __align__(8) unsigned long long mbar2;   // final combine (rank0)

    const int slice = blockIdx.x;      // 0..7, rank within the single cluster
    const int tid   = threadIdx.x;     // 0..1023
    const int row   = tid >> 5;        // warp w == row w
    const int lane  = tid & 31;

    const uint32_t mbar1_a = smem_u32(&mbar1);
    const uint32_t mbar2_a = smem_u32(&mbar2);

    // ---- issue ALL global loads first (latency hidden behind init + sync) --
    const float* prow = pred  + row * (2 * GP) + slice * SCOLS;
    const float* trow = truth + row * (2 * GP) + slice * SCOLS;
    float4 pX = ((const float4*)prow)[lane];
    float4 tX = ((const float4*)trow)[lane];
    float4 pY = ((const float4*)(prow + GP))[lane];
    float4 tY = ((const float4*)(trow + GP))[lane];

    // ---- mbarrier init while loads are in flight ----------------------------
    if (tid == 0) {
        mbar_init(mbar1_a, 1);
        mbar_expect_tx(mbar1_a, 8 * GB * 16);   // 8 ranks x 32 rows x 2 pairs x 8 B
        if (slice == 0) {
            mbar_init(mbar2_a, 1);
            mbar_expect_tx(mbar2_a, 8 * 4);     // 8 ranks x 4 B
        }
    }

    // single cluster barrier: mbarriers visible before any st.async
    asm volatile("barrier.cluster.arrive.aligned;" ::: "memory");
    asm volatile("barrier.cluster.wait.aligned;"   ::: "memory");

    // ---- Phase 1: v = p - t, stash slices, per-row partial sums ------------
    float4 vX, vY;
    vX.x = pX.x - tX.x; vX.y = pX.y - tX.y; vX.z = pX.z - tX.z; vX.w = pX.w - tX.w;
    vY.x = pY.x - tY.x; vY.y = pY.y - tY.y; vY.z = pY.z - tY.z; vY.w = pY.w - tY.w;
    ((float4*)(sv + row * SCOLS))[lane]              = vX;
    ((float4*)(sv + GB * SCOLS + row * SCOLS))[lane] = vY;

    float rsX = (vX.x + vX.y) + (vX.z + vX.w);
    float sqX = vX.x*vX.x + vX.y*vX.y + vX.z*vX.z + vX.w*vX.w;
    float rsY = (vY.x + vY.y) + (vY.z + vY.w);
    float sqY = vY.x*vY.x + vY.y*vY.y + vY.z*vY.z + vY.w*vY.w;
    #pragma unroll
    for (int off = 16; off; off >>= 1) {
        rsX += __shfl_xor_sync(0xffffffff, rsX, off);
        sqX += __shfl_xor_sync(0xffffffff, sqX, off);
        rsY += __shfl_xor_sync(0xffffffff, rsY, off);
        sqY += __shfl_xor_sync(0xffffffff, sqY, off);
    }

    // lane0 of each warp pushes this row's partials to ALL 8 ranks, ASAP
    if (lane == 0) {
        uint32_t slotX = smem_u32(&s_pX[slice][row]);
        uint32_t slotY = smem_u32(&s_pY[slice][row]);
        #pragma unroll
        for (int r = 0; r < 8; r++) {
            uint32_t mb = mapa_rank(mbar1_a, r);
            st_async_b64(mapa_rank(slotX, r), rsX, sqX, mb);
            st_async_b64(mapa_rank(slotY, r), rsY, sqY, mb);
        }
    }
    __syncthreads();     // sv fully written (needed by phase 2)

    // ---- warps 0/1: wait for partials, build rowsums + S2 ------------------
    if (tid < 64) {
        const int h = tid >> 5;          // warp0 -> X, warp1 -> Y
        mbar_wait(mbar1_a, 0);
        float rtot = 0.f, sqrow = 0.f;
        #pragma unroll
        for (int s = 0; s < 8; s++) {
            float2 m = (h == 0) ? s_pX[s][lane] : s_pY[s][lane];
            rtot  += m.x;
            sqrow += m.y;
        }
        s_rowsum[h][lane] = rtot;
        #pragma unroll
        for (int off = 16; off; off >>= 1)
            sqrow += __shfl_xor_sync(0xffffffff, sqrow, off);
        if (lane == 0) s_S2[h] = sqrow;
    }
    __syncthreads();

    // ---- Phase 2: per-anchor distance (256 anchors: 128 X + 128 Y) ---------
    float val = 0.f;
    if (tid < 2 * SCOLS) {
        const int h = tid >> 7;          // 0 = X, 1 = Y
        const int i = tid & (SCOLS - 1);
        const float* svh = sv + h * GB * SCOLS;
        float dot = 0.f, colsq = 0.f;
        #pragma unroll
        for (int b = 0; b < GB; b++) {
            float v = svh[b * SCOLS + i];
            dot   += v * s_rowsum[h][b];
            colsq += v * v;
        }
        float s = s_S2[h] - 2.0f * dot + (float)GP * colsq;
        val = sqrtf(fmaxf(s, 0.0f));
        #pragma unroll
        for (int off = 16; off; off >>= 1)
            val += __shfl_xor_sync(0xffffffff, val, off);
        if (lane == 0) s_red[tid >> 5] = val;
    }
    __syncthreads();

    // ---- tail: push block sum to rank0; rank0 combines and writes out ------
    if (tid == 0) {
        float bs = 0.f;
        #pragma unroll
        for (int w = 0; w < 8; w++) bs += s_red[w];
        st_async_b32(mapa_rank(smem_u32(&s_bsums[slice]), 0), bs,
                     mapa_rank(mbar2_a, 0));

        if (slice == 0) {
            mbar_wait(mbar2_a, 0);
            float total = 0.f;
            #pragma unroll
            for (int s = 0; s < 8; s++) total += s_bsums[s];
            *out = total * (1.0f / (float)(GB * 2));
        }
    }
    // no trailing barrier: all cross-CTA traffic is push-style and rank0
    // acknowledges receipt via its mbarrier wait before exiting.
}

extern "C" void kernel_launch(void* const* d_in, const int* in_sizes, int n_in,
                              void* d_out, int out_size)
{
    (void)in_sizes; (void)n_in; (void)out_size;
    const float* pred  = (const float*)d_in[0];
    const float* truth = (const float*)d_in[1];
    float* out = (float*)d_out;

    gcs_loss_kernel<<<8, 1024>>>(pred, truth, out);
}

// round 6
// speedup vs baseline: 1.0372x; 1.0372x over previous
#include <cuda_runtime.h>
#include <cstdint>

// ---------------------------------------------------------------------------
// Gcs_loss, expanded form:
//   v = pred - truth, halves X = v[:,:P], Y = v[:,P:]
//   s_i = S2 - 2 * dot_i + P * colsq_i,
//   dot_i = sum_b v[b,i]*rowsum[b],  colsq_i = sum_b v[b,i]^2
//   out = ( sum_i sqrt(s_i^X) + sum_i sqrt(s_i^Y) ) / (2B),  B=32, P=1024.
//
// ONE cluster of 8 CTAs; CTA r owns column slice r (128 cols) of BOTH halves.
// Single cluster.sync (overlapped with global loads). Partial exchange and
// final combine are push-style st.async + mbarrier. Phase 2 is fully
// warp-autonomous: each warp rebuilds rowsums from the pushed partials and
// broadcasts them via shfl — no intermediate smem stage, no extra barriers.
// ---------------------------------------------------------------------------

#define GB      32
#define GP      1024
#define SCOLS   128            // columns per slice (8 slices per half)

// ---------------- tiny PTX helpers ----------------
__device__ __forceinline__ uint32_t smem_u32(const void* p) {
    uint32_t a;
    asm("{ .reg .u64 t; cvta.to.shared.u64 t, %1; cvt.u32.u64 %0, t; }"
        : "=r"(a) : "l"(p));
    return a;
}
__device__ __forceinline__ uint32_t mapa_rank(uint32_t smem_addr, uint32_t rank) {
    uint32_t r;
    asm("mapa.shared::cluster.u32 %0, %1, %2;" : "=r"(r) : "r"(smem_addr), "r"(rank));
    return r;
}
__device__ __forceinline__ void mbar_init(uint32_t mbar, uint32_t count) {
    asm volatile("mbarrier.init.shared.b64 [%0], %1;" :: "r"(mbar), "r"(count) : "memory");
}
__device__ __forceinline__ void mbar_expect_tx(uint32_t mbar, uint32_t bytes) {
    asm volatile("mbarrier.arrive.expect_tx.shared.b64 _, [%0], %1;"
                 :: "r"(mbar), "r"(bytes) : "memory");
}
__device__ __forceinline__ void mbar_wait(uint32_t mbar, uint32_t parity) {
    uint32_t done;
    asm volatile(
        "{\n\t.reg .pred p;\n\t"
        "mbarrier.try_wait.parity.acquire.cta.shared::cta.b64 p, [%1], %2;\n\t"
        "selp.b32 %0, 1, 0, p;\n\t}"
        : "=r"(done) : "r"(mbar), "r"(parity) : "memory");
    if (!done) {
        asm volatile(
            "{\n\t.reg .pred P1;\n\t"
            "WL_%=:\n\t"
            "mbarrier.try_wait.parity.acquire.cta.shared::cta.b64 P1, [%0], %1, 0x989680;\n\t"
            "@P1 bra.uni WD_%=;\n\t"
            "bra.uni WL_%=;\n\t"
            "WD_%=:\n\t}"
            :: "r"(mbar), "r"(parity) : "memory");
    }
}
__device__ __forceinline__ void st_async_b64(uint32_t dst, float a, float b, uint32_t mbar) {
    float2 v = make_float2(a, b);
    unsigned long long bits = *reinterpret_cast<unsigned long long*>(&v);
    asm volatile("st.async.shared::cluster.mbarrier::complete_tx::bytes.b64 [%0], %1, [%2];"
                 :: "r"(dst), "l"(bits), "r"(mbar) : "memory");
}
__device__ __forceinline__ void st_async_b32(uint32_t dst, float a, uint32_t mbar) {
    asm volatile("st.async.shared::cluster.mbarrier::complete_tx::bytes.b32 [%0], %1, [%2];"
                 :: "r"(dst), "r"(__float_as_uint(a)), "r"(mbar) : "memory");
}

// ---------------------------------------------------------------------------

__global__ void __launch_bounds__(1024, 1) __cluster_dims__(8, 1, 1)
gcs_loss_kernel(const float* __restrict__ pred,
                const float* __restrict__ truth,
                float* __restrict__ out)
{
    __shared__ float  sv[2 * GB * SCOLS];      // 32 KB: [half][row][col]
    __shared__ float2 s_pX[8][GB];             // pushed (rowsumX, sqX) per src rank/row
    __shared__ float2 s_pY[8][GB];             // pushed (rowsumY, sqY)
    __shared__ float  s_tail[64];              // rank0: per (rank, phase2-warp) sums
    __shared__ __align__(8) unsigned long long mbar1;   // partials exchange
    __shared__ __align__(8) unsigned long long mbar2;   // final combine (rank0)

    const int slice = blockIdx.x;      // 0..7, rank within the single cluster
    const int tid   = threadIdx.x;     // 0..1023
    const int wid   = tid >> 5;        // warp w loads row w
    const int lane  = tid & 31;

    const uint32_t mbar1_a = smem_u32(&mbar1);
    const uint32_t mbar2_a = smem_u32(&mbar2);

    // ---- issue ALL global loads first (latency hidden behind init + sync) --
    const float* prow = pred  + wid * (2 * GP) + slice * SCOLS;
    const float* trow = truth + wid * (2 * GP) + slice * SCOLS;
    float4 pX = ((const float4*)prow)[lane];
    float4 tX = ((const float4*)trow)[lane];
    float4 pY = ((const float4*)(prow + GP))[lane];
    float4 tY = ((const float4*)(trow + GP))[lane];

    // ---- mbarrier init while loads are in flight ---------------------------
    if (tid == 0) {
        mbar_init(mbar1_a, 1);
        mbar_expect_tx(mbar1_a, 8 * GB * 16);   // 8 ranks x 32 rows x (X+Y) x 8 B = 4096
        if (slice == 0) {
            mbar_init(mbar2_a, 1);
            mbar_expect_tx(mbar2_a, 64 * 4);    // 8 ranks x 8 warps x 4 B
        }
    }

    // single cluster barrier: mbarriers visible before any st.async
    asm volatile("barrier.cluster.arrive.aligned;" ::: "memory");
    asm volatile("barrier.cluster.wait.aligned;"   ::: "memory");

    // ---- Phase 1: v = p - t, stash slices, per-row partial sums ------------
    float4 vX, vY;
    vX.x = pX.x - tX.x; vX.y = pX.y - tX.y; vX.z = pX.z - tX.z; vX.w = pX.w - tX.w;
    vY.x = pY.x - tY.x; vY.y = pY.y - tY.y; vY.z = pY.z - tY.z; vY.w = pY.w - tY.w;
    ((float4*)(sv + wid * SCOLS))[lane]              = vX;
    ((float4*)(sv + GB * SCOLS + wid * SCOLS))[lane] = vY;

    float rsX = (vX.x + vX.y) + (vX.z + vX.w);
    float sqX = vX.x*vX.x + vX.y*vX.y + vX.z*vX.z + vX.w*vX.w;
    float rsY = (vY.x + vY.y) + (vY.z + vY.w);
    float sqY = vY.x*vY.x + vY.y*vY.y + vY.z*vY.z + vY.w*vY.w;
    #pragma unroll
    for (int off = 16; off; off >>= 1) {
        rsX += __shfl_xor_sync(0xffffffff, rsX, off);
        sqX += __shfl_xor_sync(0xffffffff, sqX, off);
        rsY += __shfl_xor_sync(0xffffffff, rsY, off);
        sqY += __shfl_xor_sync(0xffffffff, sqY, off);
    }

    // push this row's partials to ALL 8 ranks, fanned across 16 lanes
    if (lane < 16) {
        const int r = lane & 7;
        const uint32_t mb = mapa_rank(mbar1_a, r);
        if (lane < 8) {
            st_async_b64(mapa_rank(smem_u32(&s_pX[slice][wid]), r), rsX, sqX, mb);
        } else {
            st_async_b64(mapa_rank(smem_u32(&s_pY[slice][wid]), r), rsY, sqY, mb);
        }
    }
    __syncthreads();     // sv fully written (needed by phase 2)

    // ---- Phase 2: fully warp-autonomous, warps 0..7 ------------------------
    if (wid < 8) {
        const int h = wid >> 2;                 // warps 0-3: X, 4-7: Y
        const int i = (wid & 3) * 32 + lane;    // anchor column within slice
        const float* svh = sv + h * GB * SCOLS;

        // colsq first — does NOT need the partial exchange (hides mbar wait)
        float colsq = 0.f;
        #pragma unroll
        for (int b = 0; b < GB; b++) {
            float v = svh[b * SCOLS + i];
            colsq += v * v;
        }

        // wait for partials; lane l rebuilds rowsum/sumsq of row l
        mbar_wait(mbar1_a, 0);
        const float2* part = (h == 0) ? &s_pX[0][0] : &s_pY[0][0];
        float rowsum_l = 0.f, sq_l = 0.f;
        #pragma unroll
        for (int s = 0; s < 8; s++) {
            float2 m = part[s * GB + lane];
            rowsum_l += m.x;
            sq_l     += m.y;
        }
        float S2 = sq_l;
        #pragma unroll
        for (int off = 16; off; off >>= 1)
            S2 += __shfl_xor_sync(0xffffffff, S2, off);

        // dot via register broadcast of rowsums
        float dot = 0.f;
        #pragma unroll
        for (int b = 0; b < GB; b++) {
            float v  = svh[b * SCOLS + i];
            float rb = __shfl_sync(0xffffffff, rowsum_l, b);
            dot += v * rb;
        }

        float s   = S2 - 2.0f * dot + (float)GP * colsq;
        float val = sqrtf(fmaxf(s, 0.0f));
        #pragma unroll
        for (int off = 16; off; off >>= 1)
            val += __shfl_xor_sync(0xffffffff, val, off);

        // push warp sum straight to rank0
        if (lane == 0) {
            st_async_b32(mapa_rank(smem_u32(&s_tail[slice * 8 + wid]), 0), val,
                         mapa_rank(mbar2_a, 0));
        }
        __syncwarp();

        // rank0 warp0: cooperative final combine
        if (slice == 0 && wid == 0) {
            mbar_wait(mbar2_a, 0);
            float t = s_tail[lane] + s_tail[lane + 32];
            #pragma unroll
            for (int off = 16; off; off >>= 1)
                t += __shfl_xor_sync(0xffffffff, t, off);
            if (lane == 0)
                *out = t * (1.0f / (float)(GB * 2));
        }
    }
    // no trailing barrier: all cross-CTA traffic is push-style; every rank's
    // inbound st.asyncs are acknowledged by that rank's own mbar waits.
}

extern "C" void kernel_launch(void* const* d_in, const int* in_sizes, int n_in,
                              void* d_out, int out_size)
{
    (void)in_sizes; (void)n_in; (void)out_size;
    const float* pred  = (const float*)d_in[0];
    const float* truth = (const float*)d_in[1];
    float* out = (float*)d_out;

    gcs_loss_kernel<<<8, 1024>>>(pred, truth, out);
}

// round 8
// speedup vs baseline: 1.3413x; 1.2933x over previous
#include <cuda_runtime.h>
#include <cstdint>

// ---------------------------------------------------------------------------
// Gcs_loss, expanded form:
//   v = pred - truth, halves X = v[:,:P], Y = v[:,P:]
//   s_i = S2 - 2 * dot_i + P * colsq_i,
//   dot_i = sum_b v[b,i]*rowsum[b],  colsq_i = sum_b v[b,i]^2
//   out = ( sum_i sqrt(s_i^X) + sum_i sqrt(s_i^Y) ) / (2B),  B=32, P=1024.
//
// ONE cluster of 8 CTAs, 512 threads each; CTA r owns column slice r
// (128 cols) of BOTH halves; warp w loads rows 2w, 2w+1. Single cluster.sync
// (overlapped with global loads); partial exchange and final combine are
// push-style st.async + mbarrier. Phase 2 register-caches its anchor column
// before the mbarrier wait so the post-wait path is pure FFMA+SHFL.
// ---------------------------------------------------------------------------

#define GB      32
#define GP      1024
#define SCOLS   128            // columns per slice (8 slices per half)

// ---------------- tiny PTX helpers ----------------
__device__ __forceinline__ uint32_t smem_u32(const void* p) {
    uint32_t a;
    asm("{ .reg .u64 t; cvta.to.shared.u64 t, %1; cvt.u32.u64 %0, t; }"
        : "=r"(a) : "l"(p));
    return a;
}
__device__ __forceinline__ uint32_t mapa_rank(uint32_t smem_addr, uint32_t rank) {
    uint32_t r;
    asm("mapa.shared::cluster.u32 %0, %1, %2;" : "=r"(r) : "r"(smem_addr), "r"(rank));
    return r;
}
__device__ __forceinline__ void mbar_init(uint32_t mbar, uint32_t count) {
    asm volatile("mbarrier.init.shared.b64 [%0], %1;" :: "r"(mbar), "r"(count) : "memory");
}
__device__ __forceinline__ void mbar_expect_tx(uint32_t mbar, uint32_t bytes) {
    asm volatile("mbarrier.arrive.expect_tx.shared.b64 _, [%0], %1;"
                 :: "r"(mbar), "r"(bytes) : "memory");
}
__device__ __forceinline__ void mbar_wait(uint32_t mbar, uint32_t parity) {
    uint32_t done;
    asm volatile(
        "{\n\t.reg .pred p;\n\t"
        "mbarrier.try_wait.parity.acquire.cta.shared::cta.b64 p, [%1], %2;\n\t"
        "selp.b32 %0, 1, 0, p;\n\t}"
        : "=r"(done) : "r"(mbar), "r"(parity) : "memory");
    if (!done) {
        asm volatile(
            "{\n\t.reg .pred P1;\n\t"
            "WL_%=:\n\t"
            "mbarrier.try_wait.parity.acquire.cta.shared::cta.b64 P1, [%0], %1, 0x989680;\n\t"
            "@P1 bra.uni WD_%=;\n\t"
            "bra.uni WL_%=;\n\t"
            "WD_%=:\n\t}"
            :: "r"(mbar), "r"(parity) : "memory");
    }
}
__device__ __forceinline__ void st_async_b64(uint32_t dst, float a, float b, uint32_t mbar) {
    float2 v = make_float2(a, b);
    unsigned long long bits = *reinterpret_cast<unsigned long long*>(&v);
    asm volatile("st.async.shared::cluster.mbarrier::complete_tx::bytes.b64 [%0], %1, [%2];"
                 :: "r"(dst), "l"(bits), "r"(mbar) : "memory");
}
__device__ __forceinline__ void st_async_b32(uint32_t dst, float a, uint32_t mbar) {
    asm volatile("st.async.shared::cluster.mbarrier::complete_tx::bytes.b32 [%0], %1, [%2];"
                 :: "r"(dst), "r"(__float_as_uint(a)), "r"(mbar) : "memory");
}
// warp-wide sum via shfl butterfly (result in all lanes)
__device__ __forceinline__ float warp_sum(float v) {
    #pragma unroll
    for (int off = 16; off; off >>= 1)
        v += __shfl_xor_sync(0xffffffff, v, off);
    return v;
}

// ---------------------------------------------------------------------------

__global__ void __launch_bounds__(512, 1) __cluster_dims__(8, 1, 1)
gcs_loss_kernel(const float* __restrict__ pred,
                const float* __restrict__ truth,
                float* __restrict__ out)
{
    __shared__ float  sv[2 * GB * SCOLS];      // 32 KB: [half][row][col]
    __shared__ float2 s_pX[8][GB];             // pushed (rowsumX, sqX) per src rank/row
    __shared__ float2 s_pY[8][GB];             // pushed (rowsumY, sqY)
    __shared__ float  s_tail[64];              // rank0: per (rank, phase2-warp) sums
    __shared__ __align__(8) unsigned long long mbar1;   // partials exchange
    __shared__ __align__(8) unsigned long long mbar2;   // final combine (rank0)

    const int slice = blockIdx.x;      // 0..7, rank within the single cluster
    const int tid   = threadIdx.x;     // 0..511
    const int wid   = tid >> 5;        // warp w loads rows 2w, 2w+1
    const int lane  = tid & 31;

    const uint32_t mbar1_a = smem_u32(&mbar1);
    const uint32_t mbar2_a = smem_u32(&mbar2);

    // ---- issue ALL global loads first (latency hidden behind init + sync) --
    const int r0 = 2 * wid, r1 = 2 * wid + 1;
    const float* p0 = pred  + r0 * (2 * GP) + slice * SCOLS;
    const float* t0 = truth + r0 * (2 * GP) + slice * SCOLS;
    const float* p1 = pred  + r1 * (2 * GP) + slice * SCOLS;
    const float* t1 = truth + r1 * (2 * GP) + slice * SCOLS;
    float4 pX0 = ((const float4*)p0)[lane];
    float4 tX0 = ((const float4*)t0)[lane];
    float4 pY0 = ((const float4*)(p0 + GP))[lane];
    float4 tY0 = ((const float4*)(t0 + GP))[lane];
    float4 pX1 = ((const float4*)p1)[lane];
    float4 tX1 = ((const float4*)t1)[lane];
    float4 pY1 = ((const float4*)(p1 + GP))[lane];
    float4 tY1 = ((const float4*)(t1 + GP))[lane];

    // ---- mbarrier init while loads are in flight ---------------------------
    if (tid == 0) {
        mbar_init(mbar1_a, 1);
        mbar_expect_tx(mbar1_a, 8 * GB * 16);   // 8 ranks x 32 rows x (X+Y) x 8 B
        if (slice == 0) {
            mbar_init(mbar2_a, 1);
            mbar_expect_tx(mbar2_a, 64 * 4);    // 8 ranks x 8 warps x 4 B
        }
    }

    // single cluster barrier: mbarriers visible before any st.async
    asm volatile("barrier.cluster.arrive.aligned;" ::: "memory");
    asm volatile("barrier.cluster.wait.aligned;"   ::: "memory");

    // ---- Phase 1: v = p - t, stash slices, per-row reductions --------------
    float4 vX0, vY0, vX1, vY1;
    vX0.x = pX0.x - tX0.x; vX0.y = pX0.y - tX0.y; vX0.z = pX0.z - tX0.z; vX0.w = pX0.w - tX0.w;
    vY0.x = pY0.x - tY0.x; vY0.y = pY0.y - tY0.y; vY0.z = pY0.z - tY0.z; vY0.w = pY0.w - tY0.w;
    vX1.x = pX1.x - tX1.x; vX1.y = pX1.y - tX1.y; vX1.z = pX1.z - tX1.z; vX1.w = pX1.w - tX1.w;
    vY1.x = pY1.x - tY1.x; vY1.y = pY1.y - tY1.y; vY1.z = pY1.z - tY1.z; vY1.w = pY1.w - tY1.w;
    ((float4*)(sv + r0 * SCOLS))[lane]              = vX0;
    ((float4*)(sv + GB * SCOLS + r0 * SCOLS))[lane] = vY0;
    ((float4*)(sv + r1 * SCOLS))[lane]              = vX1;
    ((float4*)(sv + GB * SCOLS + r1 * SCOLS))[lane] = vY1;

    // 8 independent warp reductions — ILP hides shfl latency
    float rsX0 = (vX0.x + vX0.y) + (vX0.z + vX0.w);
    float sqX0 = vX0.x*vX0.x + vX0.y*vX0.y + vX0.z*vX0.z + vX0.w*vX0.w;
    float rsY0 = (vY0.x + vY0.y) + (vY0.z + vY0.w);
    float sqY0 = vY0.x*vY0.x + vY0.y*vY0.y + vY0.z*vY0.z + vY0.w*vY0.w;
    float rsX1 = (vX1.x + vX1.y) + (vX1.z + vX1.w);
    float sqX1 = vX1.x*vX1.x + vX1.y*vX1.y + vX1.z*vX1.z + vX1.w*vX1.w;
    float rsY1 = (vY1.x + vY1.y) + (vY1.z + vY1.w);
    float sqY1 = vY1.x*vY1.x + vY1.y*vY1.y + vY1.z*vY1.z + vY1.w*vY1.w;
    #pragma unroll
    for (int off = 16; off; off >>= 1) {
        rsX0 += __shfl_xor_sync(0xffffffff, rsX0, off);
        sqX0 += __shfl_xor_sync(0xffffffff, sqX0, off);
        rsY0 += __shfl_xor_sync(0xffffffff, rsY0, off);
        sqY0 += __shfl_xor_sync(0xffffffff, sqY0, off);
        rsX1 += __shfl_xor_sync(0xffffffff, rsX1, off);
        sqX1 += __shfl_xor_sync(0xffffffff, sqX1, off);
        rsY1 += __shfl_xor_sync(0xffffffff, rsY1, off);
        sqY1 += __shfl_xor_sync(0xffffffff, sqY1, off);
    }

    // push both rows' partials to ALL 8 ranks, fanned across all 32 lanes
    {
        const int r = lane & 7;                  // destination rank
        const int which = lane >> 3;             // 0: Xr0, 1: Yr0, 2: Xr1, 3: Yr1
        const uint32_t mb = mapa_rank(mbar1_a, r);
        uint32_t slot; float a, b;
        switch (which) {
            case 0:  slot = smem_u32(&s_pX[slice][r0]); a = rsX0; b = sqX0; break;
            case 1:  slot = smem_u32(&s_pY[slice][r0]); a = rsY0; b = sqY0; break;
            case 2:  slot = smem_u32(&s_pX[slice][r1]); a = rsX1; b = sqX1; break;
            default: slot = smem_u32(&s_pY[slice][r1]); a = rsY1; b = sqY1; break;
        }
        st_async_b64(mapa_rank(slot, r), a, b, mb);
    }
    __syncthreads();     // sv fully written (needed by phase 2)

    // ---- Phase 2: fully warp-autonomous, warps 0..7 ------------------------
    if (wid < 8) {
        const int h = wid >> 2;                 // warps 0-3: X, 4-7: Y
        const int i = (wid & 3) * 32 + lane;    // anchor column within slice
        const float* svh = sv + h * GB * SCOLS;

        // register-cache the anchor column + colsq BEFORE the mbar wait
        float vcol[GB];
        float colsq = 0.f;
        #pragma unroll
        for (int b = 0; b < GB; b++) {
            vcol[b] = svh[b * SCOLS + i];
            colsq  += vcol[b] * vcol[b];
        }

        // wait for partials; lane l rebuilds rowsum/sumsq of row l
        mbar_wait(mbar1_a, 0);
        const float2* part = (h == 0) ? &s_pX[0][0] : &s_pY[0][0];
        float rowsum_l = 0.f, sq_l = 0.f;
        #pragma unroll
        for (int s = 0; s < 8; s++) {
            float2 m = part[s * GB + lane];
            rowsum_l += m.x;
            sq_l     += m.y;
        }
        float S2 = warp_sum(sq_l);

        // dot via register broadcast of rowsums — pure FFMA + SHFL
        float dot = 0.f;
        #pragma unroll
        for (int b = 0; b < GB; b++)
            dot += vcol[b] * __shfl_sync(0xffffffff, rowsum_l, b);

        float s   = S2 - 2.0f * dot + (float)GP * colsq;
        float val = warp_sum(sqrtf(fmaxf(s, 0.0f)));

        // push warp sum straight to rank0
        if (lane == 0) {
            st_async_b32(mapa_rank(smem_u32(&s_tail[slice * 8 + wid]), 0), val,
                         mapa_rank(mbar2_a, 0));
        }

        // rank0 warp0: cooperative final combine
        if (slice == 0 && wid == 0) {
            mbar_wait(mbar2_a, 0);
            float t = s_tail[lane] + s_tail[lane + 32];
            t = warp_sum(t);
            if (lane == 0)
                *out = t * (1.0f / (float)(GB * 2));
        }
    }
    // no trailing barrier: all cross-CTA traffic is push-style; every rank's
    // inbound st.asyncs are acknowledged by that rank's own mbar waits.
}

extern "C" void kernel_launch(void* const* d_in, const int* in_sizes, int n_in,
                              void* d_out, int out_size)
{
    (void)in_sizes; (void)n_in; (void)out_size;
    const float* pred  = (const float*)d_in[0];
    const float* truth = (const float*)d_in[1];
    float* out = (float*)d_out;

    gcs_loss_kernel<<<8, 512>>>(pred, truth, out);
}